// round 1
// baseline (speedup 1.0000x reference)
#include <cuda_runtime.h>

#define GRIDW 32
#define BATCH 64
#define NPTS  16384
#define GCNT  (GRIDW*GRIDW*GRIDW)
#define TPB   256
#define BLOCKS_PER_BATCH (NPTS / TPB)   // 64

__device__ double g_acc;

__global__ void sdl_zero_kernel() { g_acc = 0.0; }

__global__ void sdl_fin_kernel(float* out) {
    out[0] = (float)(g_acc / ((double)BATCH * (double)NPTS));
}

__device__ __forceinline__ float symdist(float sx, float sy, float sz,
                                         const float* __restrict__ cb) {
    int ix = (int)floorf(fminf(fmaxf(sx, 0.f), 31.f));
    int iy = (int)floorf(fminf(fmaxf(sy, 0.f), 31.f));
    int iz = (int)floorf(fminf(fmaxf(sz, 0.f), 31.f));
    int flat = (ix << 10) + (iy << 5) + iz;
    const float* c = cb + flat * 3;
    float dx = sx - __ldg(c + 0);
    float dy = sy - __ldg(c + 1);
    float dz = sz - __ldg(c + 2);
    return sqrtf(dx * dx + dy * dy + dz * dz);
}

__global__ __launch_bounds__(TPB)
void sdl_main_kernel(const float* __restrict__ prm,
                     const float* __restrict__ points,
                     const float* __restrict__ closest) {
    // per-batch constants: 3 planes (nx,ny,nz,d,inv_nn) + 3 quats (w,x,y,z,inv_norm)
    __shared__ float sp[3][5];
    __shared__ float sq[3][5];
    __shared__ float spts[TPB * 3];
    __shared__ float sred[TPB / 32];

    const int b  = blockIdx.x >> 6;             // / BLOCKS_PER_BATCH
    const int n0 = (blockIdx.x & 63) * TPB;
    const float* op = prm + b * 24;

    if (threadIdx.x == 0) {
        #pragma unroll
        for (int p = 0; p < 3; p++) {
            float nx = op[p*4+0], ny = op[p*4+1], nz = op[p*4+2], d = op[p*4+3];
            sp[p][0] = nx; sp[p][1] = ny; sp[p][2] = nz; sp[p][3] = d;
            sp[p][4] = __frcp_rn(nx*nx + ny*ny + nz*nz);
        }
        #pragma unroll
        for (int q = 0; q < 3; q++) {
            float w = op[12+q*4+0], x = op[12+q*4+1], y = op[12+q*4+2], z = op[12+q*4+3];
            sq[q][0] = w; sq[q][1] = x; sq[q][2] = y; sq[q][3] = z;
            sq[q][4] = rsqrtf(w*w + x*x + y*y + z*z);
        }
    }

    // coalesced stage of 256 points (768 floats) into shared
    const float* pbase = points + ((long long)b * NPTS + n0) * 3;
    #pragma unroll
    for (int i = 0; i < 3; i++)
        spts[threadIdx.x + i * TPB] = pbase[threadIdx.x + i * TPB];
    __syncthreads();

    const float px = spts[threadIdx.x * 3 + 0];
    const float py = spts[threadIdx.x * 3 + 1];
    const float pz = spts[threadIdx.x * 3 + 2];
    const float* cb = closest + (long long)b * (GCNT * 3);

    float acc = 0.f;

    // 3 plane reflections: refl = p - 2*((n.p + d)*inv_nn)*n
    #pragma unroll
    for (int p = 0; p < 3; p++) {
        float nx = sp[p][0], ny = sp[p][1], nz = sp[p][2], d = sp[p][3], inv = sp[p][4];
        float dis = (nx * px + ny * py + nz * pz + d) * inv;
        float k = 2.f * dis;
        float sx = px - k * nx;
        float sy = py - k * ny;
        float sz = pz - k * nz;
        acc += symdist(sx, sy, sz, cb);
    }

    // 3 quaternion rotations: rot = vec( (R*qhat) * conj(R)/|R| )
    #pragma unroll
    for (int q = 0; q < 3; q++) {
        float w = sq[q][0], x = sq[q][1], y = sq[q][2], z = sq[q][3], invn = sq[q][4];
        // T = R * (0, p):  Tw = -(Rv.p);  Tv = w*p + Rv x p
        float Tw  = -(x * px + y * py + z * pz);
        float Tvx = w * px + (y * pz - z * py);
        float Tvy = w * py + (z * px - x * pz);
        float Tvz = w * pz + (x * py - y * px);
        // rot = invn * ( -Tw*Rv + w*Tv - Tv x Rv )
        float sx = invn * (-Tw * x + w * Tvx - (Tvy * z - Tvz * y));
        float sy = invn * (-Tw * y + w * Tvy - (Tvz * x - Tvx * z));
        float sz = invn * (-Tw * z + w * Tvz - (Tvx * y - Tvy * x));
        acc += symdist(sx, sy, sz, cb);
    }

    // warp reduce
    #pragma unroll
    for (int o = 16; o; o >>= 1) acc += __shfl_xor_sync(0xffffffffu, acc, o);
    if ((threadIdx.x & 31) == 0) sred[threadIdx.x >> 5] = acc;
    __syncthreads();

    if (threadIdx.x < 32) {
        float v = (threadIdx.x < (TPB / 32)) ? sred[threadIdx.x] : 0.f;
        #pragma unroll
        for (int o = 4; o; o >>= 1) v += __shfl_xor_sync(0xffffffffu, v, o);
        if (threadIdx.x == 0) atomicAdd(&g_acc, (double)v);
    }
}

extern "C" void kernel_launch(void* const* d_in, const int* in_sizes, int n_in,
                              void* d_out, int out_size) {
    const float* prm     = (const float*)d_in[0];   // (64, 6, 4)
    const float* points  = (const float*)d_in[1];   // (64, 16384, 3)
    const float* closest = (const float*)d_in[2];   // (64, 32768, 3)
    float* out = (float*)d_out;

    sdl_zero_kernel<<<1, 1>>>();
    sdl_main_kernel<<<BATCH * BLOCKS_PER_BATCH, TPB>>>(prm, points, closest);
    sdl_fin_kernel<<<1, 1>>>(out);
}

// round 2
// speedup vs baseline: 1.2391x; 1.2391x over previous
#include <cuda_runtime.h>

#define GRIDW 32
#define BATCH 64
#define NPTS  16384
#define GCNT  (GRIDW*GRIDW*GRIDW)
#define TPB   256
#define MAIN_GRID (BATCH * (NPTS / TPB))   // 4096

__device__ double   g_acc = 0.0;
__device__ unsigned g_cnt = 0u;
__device__ float4   g_packed[BATCH * GCNT];   // 33.5 MB static scratch

// ---------------- repack: (B, G, 3) f32 -> float4 table ----------------
__global__ __launch_bounds__(TPB)
void sdl_repack_kernel(const float* __restrict__ closest) {
    int i = blockIdx.x * TPB + threadIdx.x;     // cell index over BATCH*GCNT
    const float* s = closest + (long long)i * 3;
    float4 v;
    v.x = s[0]; v.y = s[1]; v.z = s[2]; v.w = 0.f;
    g_packed[i] = v;
}

__device__ __forceinline__ float sqrt_approx(float x) {
    float r;
    asm("sqrt.approx.f32 %0, %1;" : "=f"(r) : "f"(x));
    return r;
}

__device__ __forceinline__ int cell_clamp(float s) {
    return __float2int_rd(fminf(fmaxf(s, 0.f), 31.f));
}

// ---------------- main: transform + gather + reduce + finalize ----------------
__global__ __launch_bounds__(TPB)
void sdl_main_kernel(const float* __restrict__ prm,
                     const float* __restrict__ points,
                     float* __restrict__ out) {
    __shared__ float sp[3][5];     // plane: nx,ny,nz,d,inv_nn
    __shared__ float sq[3][5];     // quat:  w,x,y,z,inv_norm
    __shared__ float spts[TPB * 3];
    __shared__ float sred[TPB / 32];

    const int b  = blockIdx.x >> 6;
    const int n0 = (blockIdx.x & 63) * TPB;
    const float* op = prm + b * 24;

    if (threadIdx.x == 0) {
        #pragma unroll
        for (int p = 0; p < 3; p++) {
            float nx = op[p*4+0], ny = op[p*4+1], nz = op[p*4+2], d = op[p*4+3];
            sp[p][0] = nx; sp[p][1] = ny; sp[p][2] = nz; sp[p][3] = d;
            sp[p][4] = __frcp_rn(nx*nx + ny*ny + nz*nz);
        }
        #pragma unroll
        for (int q = 0; q < 3; q++) {
            float w = op[12+q*4+0], x = op[12+q*4+1], y = op[12+q*4+2], z = op[12+q*4+3];
            sq[q][0] = w; sq[q][1] = x; sq[q][2] = y; sq[q][3] = z;
            sq[q][4] = rsqrtf(w*w + x*x + y*y + z*z);
        }
    }

    const float* pbase = points + ((long long)b * NPTS + n0) * 3;
    #pragma unroll
    for (int i = 0; i < 3; i++)
        spts[threadIdx.x + i * TPB] = pbase[threadIdx.x + i * TPB];
    __syncthreads();

    const float px = spts[threadIdx.x * 3 + 0];
    const float py = spts[threadIdx.x * 3 + 1];
    const float pz = spts[threadIdx.x * 3 + 2];
    const float4* __restrict__ cb = g_packed + (long long)b * GCNT;

    // ---- compute all 6 symmetric images first (max MLP on the gathers) ----
    float sx[6], sy[6], sz[6];

    #pragma unroll
    for (int p = 0; p < 3; p++) {
        float nx = sp[p][0], ny = sp[p][1], nz = sp[p][2], d = sp[p][3], inv = sp[p][4];
        float k = 2.f * ((nx * px + ny * py + nz * pz + d) * inv);
        sx[p] = px - k * nx;
        sy[p] = py - k * ny;
        sz[p] = pz - k * nz;
    }

    #pragma unroll
    for (int q = 0; q < 3; q++) {
        float w = sq[q][0], x = sq[q][1], y = sq[q][2], z = sq[q][3], invn = sq[q][4];
        float Tw  = -(x * px + y * py + z * pz);
        float Tvx = w * px + (y * pz - z * py);
        float Tvy = w * py + (z * px - x * pz);
        float Tvz = w * pz + (x * py - y * px);
        sx[3+q] = invn * (-Tw * x + w * Tvx - (Tvy * z - Tvz * y));
        sy[3+q] = invn * (-Tw * y + w * Tvy - (Tvz * x - Tvx * z));
        sz[3+q] = invn * (-Tw * z + w * Tvz - (Tvx * y - Tvy * x));
    }

    // ---- issue all 6 gathers back-to-back ----
    float4 cp[6];
    #pragma unroll
    for (int s = 0; s < 6; s++) {
        int flat = (cell_clamp(sx[s]) << 10) + (cell_clamp(sy[s]) << 5) + cell_clamp(sz[s]);
        cp[s] = __ldg(&cb[flat]);
    }

    float acc = 0.f;
    #pragma unroll
    for (int s = 0; s < 6; s++) {
        float dx = sx[s] - cp[s].x;
        float dy = sy[s] - cp[s].y;
        float dz = sz[s] - cp[s].z;
        acc += sqrt_approx(dx * dx + dy * dy + dz * dz);
    }

    // ---- block reduce ----
    #pragma unroll
    for (int o = 16; o; o >>= 1) acc += __shfl_xor_sync(0xffffffffu, acc, o);
    if ((threadIdx.x & 31) == 0) sred[threadIdx.x >> 5] = acc;
    __syncthreads();

    if (threadIdx.x == 0) {
        float v = 0.f;
        #pragma unroll
        for (int i = 0; i < TPB / 32; i++) v += sred[i];
        atomicAdd(&g_acc, (double)v);
        __threadfence();
        unsigned t = atomicAdd(&g_cnt, 1u);
        if (t == MAIN_GRID - 1) {           // last block: finalize + self-reset
            __threadfence();
            double s = g_acc;
            out[0] = (float)(s / ((double)BATCH * (double)NPTS));
            g_acc = 0.0;
            g_cnt = 0u;
            __threadfence();
        }
    }
}

extern "C" void kernel_launch(void* const* d_in, const int* in_sizes, int n_in,
                              void* d_out, int out_size) {
    const float* prm     = (const float*)d_in[0];   // (64, 6, 4)
    const float* points  = (const float*)d_in[1];   // (64, 16384, 3)
    const float* closest = (const float*)d_in[2];   // (64, 32768, 3)
    float* out = (float*)d_out;

    sdl_repack_kernel<<<(BATCH * GCNT) / TPB, TPB>>>(closest);
    sdl_main_kernel<<<MAIN_GRID, TPB>>>(prm, points, out);
}

// round 3
// speedup vs baseline: 1.3154x; 1.0615x over previous
#include <cuda_runtime.h>
#include <cuda_fp16.h>

#define GRIDW 32
#define BATCH 64
#define NPTS  16384
#define GCNT  (GRIDW*GRIDW*GRIDW)
#define TPB   256
#define PPT   2                              // points per thread
#define PTS_PER_BLOCK (TPB * PPT)            // 512
#define BLOCKS_PER_BATCH (NPTS / PTS_PER_BLOCK)   // 32
#define MAIN_GRID (BATCH * BLOCKS_PER_BATCH)      // 2048

__device__ double   g_acc = 0.0;
__device__ unsigned g_cnt = 0u;
__device__ uint2    g_packed[BATCH * GCNT];   // half4 cells: 16.8 MB static scratch

// ---------------- repack: (B, G, 3) f32 -> half4 (8B) table ----------------
__global__ __launch_bounds__(TPB)
void sdl_repack_kernel(const float* __restrict__ closest) {
    int i = blockIdx.x * TPB + threadIdx.x;     // cell index over BATCH*GCNT
    const float* s = closest + (long long)i * 3;
    __half2 xy = __floats2half2_rn(s[0], s[1]);
    __half2 zp = __floats2half2_rn(s[2], 0.f);
    uint2 v;
    v.x = *reinterpret_cast<unsigned*>(&xy);
    v.y = *reinterpret_cast<unsigned*>(&zp);
    g_packed[i] = v;
}

__device__ __forceinline__ float sqrt_approx(float x) {
    float r;
    asm("sqrt.approx.f32 %0, %1;" : "=f"(r) : "f"(x));
    return r;
}

__device__ __forceinline__ int cell_clamp(float s) {
    return __float2int_rd(fminf(fmaxf(s, 0.f), 31.f));
}

// ---------------- main: transform + gather + reduce + finalize ----------------
__global__ __launch_bounds__(TPB)
void sdl_main_kernel(const float* __restrict__ prm,
                     const float* __restrict__ points,
                     float* __restrict__ out) {
    __shared__ float sp[3][5];     // plane: nx,ny,nz,d,inv_nn
    __shared__ float sq[3][5];     // quat:  w,x,y,z,inv_norm
    __shared__ float spts[PTS_PER_BLOCK * 3];
    __shared__ float sred[TPB / 32];

    const int b  = blockIdx.x >> 5;                 // / BLOCKS_PER_BATCH
    const int n0 = (blockIdx.x & 31) * PTS_PER_BLOCK;
    const float* op = prm + b * 24;

    if (threadIdx.x == 0) {
        #pragma unroll
        for (int p = 0; p < 3; p++) {
            float nx = op[p*4+0], ny = op[p*4+1], nz = op[p*4+2], d = op[p*4+3];
            sp[p][0] = nx; sp[p][1] = ny; sp[p][2] = nz; sp[p][3] = d;
            sp[p][4] = __frcp_rn(nx*nx + ny*ny + nz*nz);
        }
        #pragma unroll
        for (int q = 0; q < 3; q++) {
            float w = op[12+q*4+0], x = op[12+q*4+1], y = op[12+q*4+2], z = op[12+q*4+3];
            sq[q][0] = w; sq[q][1] = x; sq[q][2] = y; sq[q][3] = z;
            sq[q][4] = rsqrtf(w*w + x*x + y*y + z*z);
        }
    }

    const float* pbase = points + ((long long)b * NPTS + n0) * 3;
    #pragma unroll
    for (int i = 0; i < 6; i++)
        spts[threadIdx.x + i * TPB] = pbase[threadIdx.x + i * TPB];
    __syncthreads();

    const uint2* __restrict__ cb = g_packed + (long long)b * GCNT;

    // ---- compute all 12 symmetric images (2 points x 6 syms) ----
    float sx[PPT][6], sy[PPT][6], sz[PPT][6];

    #pragma unroll
    for (int t = 0; t < PPT; t++) {
        const int pi = threadIdx.x + t * TPB;
        const float px = spts[pi * 3 + 0];
        const float py = spts[pi * 3 + 1];
        const float pz = spts[pi * 3 + 2];

        #pragma unroll
        for (int p = 0; p < 3; p++) {
            float nx = sp[p][0], ny = sp[p][1], nz = sp[p][2], d = sp[p][3], inv = sp[p][4];
            float k = 2.f * ((nx * px + ny * py + nz * pz + d) * inv);
            sx[t][p] = px - k * nx;
            sy[t][p] = py - k * ny;
            sz[t][p] = pz - k * nz;
        }
        #pragma unroll
        for (int q = 0; q < 3; q++) {
            float w = sq[q][0], x = sq[q][1], y = sq[q][2], z = sq[q][3], invn = sq[q][4];
            float Tw  = -(x * px + y * py + z * pz);
            float Tvx = w * px + (y * pz - z * py);
            float Tvy = w * py + (z * px - x * pz);
            float Tvz = w * pz + (x * py - y * px);
            sx[t][3+q] = invn * (-Tw * x + w * Tvx - (Tvy * z - Tvz * y));
            sy[t][3+q] = invn * (-Tw * y + w * Tvy - (Tvz * x - Tvx * z));
            sz[t][3+q] = invn * (-Tw * z + w * Tvz - (Tvx * y - Tvy * x));
        }
    }

    // ---- issue all 12 gathers back-to-back (max MLP) ----
    uint2 cp[PPT][6];
    #pragma unroll
    for (int t = 0; t < PPT; t++)
        #pragma unroll
        for (int s = 0; s < 6; s++) {
            int flat = (cell_clamp(sx[t][s]) << 10) + (cell_clamp(sy[t][s]) << 5)
                     + cell_clamp(sz[t][s]);
            cp[t][s] = __ldg(&cb[flat]);
        }

    float acc = 0.f;
    #pragma unroll
    for (int t = 0; t < PPT; t++)
        #pragma unroll
        for (int s = 0; s < 6; s++) {
            __half2 hxy = *reinterpret_cast<__half2*>(&cp[t][s].x);
            __half2 hzp = *reinterpret_cast<__half2*>(&cp[t][s].y);
            float2 cxy = __half22float2(hxy);
            float  cz  = __low2float(hzp);
            float dx = sx[t][s] - cxy.x;
            float dy = sy[t][s] - cxy.y;
            float dz = sz[t][s] - cz;
            acc += sqrt_approx(dx * dx + dy * dy + dz * dz);
        }

    // ---- block reduce ----
    #pragma unroll
    for (int o = 16; o; o >>= 1) acc += __shfl_xor_sync(0xffffffffu, acc, o);
    if ((threadIdx.x & 31) == 0) sred[threadIdx.x >> 5] = acc;
    __syncthreads();

    if (threadIdx.x == 0) {
        float v = 0.f;
        #pragma unroll
        for (int i = 0; i < TPB / 32; i++) v += sred[i];
        atomicAdd(&g_acc, (double)v);
        __threadfence();
        unsigned t = atomicAdd(&g_cnt, 1u);
        if (t == MAIN_GRID - 1) {           // last block: finalize + self-reset
            __threadfence();
            double s = g_acc;
            out[0] = (float)(s / ((double)BATCH * (double)NPTS));
            g_acc = 0.0;
            g_cnt = 0u;
            __threadfence();
        }
    }
}

extern "C" void kernel_launch(void* const* d_in, const int* in_sizes, int n_in,
                              void* d_out, int out_size) {
    const float* prm     = (const float*)d_in[0];   // (64, 6, 4)
    const float* points  = (const float*)d_in[1];   // (64, 16384, 3)
    const float* closest = (const float*)d_in[2];   // (64, 32768, 3)
    float* out = (float*)d_out;

    sdl_repack_kernel<<<(BATCH * GCNT) / TPB, TPB>>>(closest);
    sdl_main_kernel<<<MAIN_GRID, TPB>>>(prm, points, out);
}